// round 1
// baseline (speedup 1.0000x reference)
#include <cuda_runtime.h>

#define SGRID 14
#define BATCH 4096
#define NCELLS (BATCH * SGRID * SGRID)   // 802816
#define THREADS 256

__global__ void init_out_kernel(float* out) {
    if (threadIdx.x == 0 && blockIdx.x == 0) out[0] = 0.0f;
}

__global__ void __launch_bounds__(THREADS)
yolo_loss_kernel(const float* __restrict__ pred,
                 const float* __restrict__ targ,
                 float* __restrict__ out)
{
    int cell = blockIdx.x * blockDim.x + threadIdx.x;
    float loss = 0.0f;

    if (cell < NCELLS) {
        const float2* pp = reinterpret_cast<const float2*>(pred + (size_t)cell * 30);
        const float2* tp = reinterpret_cast<const float2*>(targ + (size_t)cell * 30);
        float p[30], t[30];
#pragma unroll
        for (int i = 0; i < 15; i++) {
            float2 v = __ldg(pp + i);
            p[2*i] = v.x; p[2*i+1] = v.y;
            float2 w = __ldg(tp + i);
            t[2*i] = w.x; t[2*i+1] = w.y;
        }

        bool obj = (t[4] > 0.0f);   // target conf is exactly 0.0 or 1.0

        if (obj) {
            // ---- class loss: sum_{c=10..29} (p-t)^2 ----
            float cls = 0.0f;
#pragma unroll
            for (int c = 10; c < 30; c++) {
                float d = p[c] - t[c];
                cls = fmaf(d, d, cls);
            }

            // ---- IoU of both pred boxes vs target box 0 ----
            const float invS = 1.0f / (float)SGRID;
            float tcx = t[0] * invS, tcy = t[1] * invS;
            float t1x = tcx - t[2] * 0.5f, t2x = tcx + t[2] * 0.5f;
            float t1y = tcy - t[3] * 0.5f, t2y = tcy + t[3] * 0.5f;
            float area_t = (t2x - t1x) * (t2y - t1y);

            float iou0, iou1;
#pragma unroll
            for (int b = 0; b < 2; b++) {
                float bx = (b == 0) ? p[0] : p[5];
                float by = (b == 0) ? p[1] : p[6];
                float bw = (b == 0) ? p[2] : p[7];
                float bh = (b == 0) ? p[3] : p[8];
                float cx = bx * invS, cy = by * invS;
                float p1x = cx - bw * 0.5f, p2x = cx + bw * 0.5f;
                float p1y = cy - bh * 0.5f, p2y = cy + bh * 0.5f;
                float ltx = fmaxf(p1x, t1x), lty = fmaxf(p1y, t1y);
                float rbx = fminf(p2x, t2x), rby = fminf(p2y, t2y);
                float wx = fmaxf(rbx - ltx, 0.0f);
                float wy = fmaxf(rby - lty, 0.0f);
                float inter = wx * wy;
                float area_p = (p2x - p1x) * (p2y - p1y);
                float iou = inter / (area_p + area_t - inter);
                if (b == 0) iou0 = iou; else iou1 = iou;
            }

            bool pick1 = (iou0 <= iou1);
            float iou_best = pick1 ? iou1 : iou0;

            // selected pred box (all 5) and selected TARGET box (all 5)
            float psx = pick1 ? p[5] : p[0];
            float psy = pick1 ? p[6] : p[1];
            float psw = pick1 ? p[7] : p[2];
            float psh = pick1 ? p[8] : p[3];
            float psc = pick1 ? p[9] : p[4];
            float tsx = pick1 ? t[5] : t[0];
            float tsy = pick1 ? t[6] : t[1];
            float tsw = pick1 ? t[7] : t[2];
            float tsh = pick1 ? t[8] : t[3];

            float dx = psx - tsx, dy = psy - tsy;
            float dw = sqrtf(psw) - sqrtf(tsw);
            float dh = sqrtf(psh) - sqrtf(tsh);
            float reg = dx*dx + dy*dy + dw*dw + dh*dh;

            float dc = psc - iou_best;

            loss = cls + 5.0f * reg + dc * dc;
        } else {
            // ---- no-object loss on both confidences ----
            float d4 = p[4] - t[4];
            float d9 = p[9] - t[9];
            loss = 0.5f * (d4 * d4 + d9 * d9);
        }
    }

    // ---- reduction: warp shfl -> smem -> one atomic per block ----
#pragma unroll
    for (int o = 16; o > 0; o >>= 1)
        loss += __shfl_xor_sync(0xffffffffu, loss, o);

    __shared__ float warp_sums[THREADS / 32];
    int wid = threadIdx.x >> 5;
    int lid = threadIdx.x & 31;
    if (lid == 0) warp_sums[wid] = loss;
    __syncthreads();

    if (wid == 0) {
        loss = (lid < THREADS / 32) ? warp_sums[lid] : 0.0f;
#pragma unroll
        for (int o = (THREADS / 64); o > 0; o >>= 1)
            loss += __shfl_xor_sync(0xffffffffu, loss, o);
        if (lid == 0)
            atomicAdd(out, loss * (1.0f / (float)BATCH));
    }
}

extern "C" void kernel_launch(void* const* d_in, const int* in_sizes, int n_in,
                              void* d_out, int out_size)
{
    const float* pred = (const float*)d_in[0];
    const float* targ = (const float*)d_in[1];
    float* out = (float*)d_out;
    (void)in_sizes; (void)n_in; (void)out_size;

    init_out_kernel<<<1, 32>>>(out);
    int blocks = (NCELLS + THREADS - 1) / THREADS;   // 3136
    yolo_loss_kernel<<<blocks, THREADS>>>(pred, targ, out);
}